// round 16
// baseline (speedup 1.0000x reference)
#include <cuda_runtime.h>
#include <cuda_fp16.h>

#define B_ 64
#define T_ 1024
#define C_ 2
#define N_ 128

// Scratch (static __device__: allowed; no dynamic allocation).
__device__ float g_af[B_ * C_ * N_];   // alpha_hat_m  (forward, normalized)
__device__ float g_bt[B_ * C_ * N_];   // beta_tilde_m (backward, normalized, * em)
__device__ int   g_kf[B_ * C_];
__device__ int   g_kb[B_ * C_];
__device__ int   g_done[B_ * C_];      // zero-init; combiner resets to 0 each run

// fp16 dot over 128 elements, fp16 epilogue: total in BOTH halves of result.
__device__ __forceinline__ __half2 dot128_h16(const __half* rbuf, const __half2* e2h) {
    const uint4* pv = reinterpret_cast<const uint4*>(rbuf);
    __half2 a0 = __float2half2_rn(0.f), a1 = a0, a2 = a0, a3 = a0;
#pragma unroll
    for (int k = 0; k < 16; ++k) {
        uint4 v = pv[k];
        a0 = __hfma2(e2h[4 * k + 0], *reinterpret_cast<const __half2*>(&v.x), a0);
        a1 = __hfma2(e2h[4 * k + 1], *reinterpret_cast<const __half2*>(&v.y), a1);
        a2 = __hfma2(e2h[4 * k + 2], *reinterpret_cast<const __half2*>(&v.z), a2);
        a3 = __hfma2(e2h[4 * k + 3], *reinterpret_cast<const __half2*>(&v.w), a3);
    }
    __half2 A  = __hadd2(a0, a1);
    __half2 Bb = __hadd2(a2, a3);
    __half2 Cc = __hadd2(A, Bb);
    return __hadd2(Cc, __lowhigh2highlow(Cc));
}

// Single fused kernel: per-CTA scheduling (R14 symmetric assignment), the
// half-chain scan, and an atomic-flag fused combine (threadFenceReduction
// pattern) by whichever half-chain CTA of each chain finishes second.
__global__ void __launch_bounds__(128, 2)
crf_bidir_kernel(const float* __restrict__ emissions,   // [B,T,C,N]
                 const int*   __restrict__ lengths,     // [B]
                 const float* __restrict__ trans,       // [1,C,N,N]
                 const float* __restrict__ start_t,     // [1,C,N]
                 const float* __restrict__ end_t,       // [1,C,N]
                 float*       __restrict__ out)         // [B,C]
{
    const int j = threadIdx.x;

    __shared__ int sL[128];
    __shared__ int sItem;
    __shared__ __align__(16) __half r_h[2][N_];
    __shared__ float red_sh[4];
    __shared__ int sFlag;

    // ---- fused scheduler: R14 symmetric assignment, recomputed per CTA ----
    // item i: role=i>>7, bc=i&127, steps = role ? L-m : m, m = L>>1, L = len-1.
    // rank by steps desc (tie: lower i). bid: rank<40 -> 108+rank (solo SMs);
    // rank<148 -> rank-40; else 148+(255-rank)  (pair longest-with-shortest,
    // since bid k and bid k+148 share an SM via LUT_classic[bid % 148]).
    sL[j] = lengths[j >> 1] - 1;     // thread j loads chain j's L
    __syncthreads();
#pragma unroll
    for (int q = 0; q < 2; ++q) {
        const int it    = 2 * j + q;
        const int bcI   = it & 127;
        const int roleI = it >> 7;
        const int L     = sL[bcI];
        const int mI    = L >> 1;
        const int steps = roleI ? (L - mI) : mI;
        int rank = 0;
#pragma unroll 1
        for (int k = 0; k < 256; ++k) {
            int Lk = sL[k & 127];
            int mk = Lk >> 1;
            int sk = (k >> 7) ? (Lk - mk) : mk;
            rank += (sk > steps) || (sk == steps && k < it);
        }
        int bid = (rank < 40) ? (108 + rank)
                              : (rank < 148 ? rank - 40 : 148 + (255 - rank));
        if (bid == (int)blockIdx.x) sItem = it;
    }
    __syncthreads();

    const int item = sItem;
    const int role = item >> 7;           // 0 = forward, 1 = backward
    const int bc   = item & 127;
    const int b    = bc >> 1;
    const int c    = bc & 1;
    const int len  = lengths[b];          // in [T/2, T]
    const int m    = (len - 1) >> 1;      // symmetric meeting point

    const float* ebase = emissions + ((size_t)b * T_ * C_ + c) * N_ + j;
    const int estride = C_ * N_;
    int kacc = 0;
    float ering[8];

    if (role == 0) {
        // ---------------- FORWARD: steps t = 1..m ----------------
        __half2 e2h[64];   // (E[2q,j], E[2q+1,j]) : column j of E
        {
            const float* tb = trans + (size_t)c * N_ * N_ + j;
#pragma unroll
            for (int q = 0; q < 64; ++q) {
                float lo = __expf(tb[(size_t)(2 * q) * N_]);
                float hi = __expf(tb[(size_t)(2 * q + 1) * N_]);
                e2h[q] = __floats2half2_rn(lo, hi);
            }
        }
        r_h[0][j] = __float2half_rn(__expf(start_t[c * N_ + j] + ebase[0]));
        __syncthreads();
#pragma unroll
        for (int d = 1; d <= 8; ++d)
            ering[d & 7] = __ldg(ebase + (size_t)d * estride);

        const int fend = m + 1;
        int t = 1;
#pragma unroll 1
        for (; t + 7 < fend; t += 8) {
#pragma unroll
            for (int u = 0; u < 8; ++u) {
                const int cur  = (1 + u) & 1;
                const int prv  = cur ^ 1;
                const int slot = (1 + u) & 7;
                unsigned short ub = __half_as_ushort(r_h[prv][0]);
                int   ke  = (ub >> 10) & 0x1f;
                float inv = __int_as_float((131 - ke) << 23);   // 2^(4-ke)
                kacc += ke;
                float em = __expf(ering[slot]);
                int tt = t + u + 8; tt = (tt > T_ - 1) ? (T_ - 1) : tt;
                ering[slot] = __ldg(ebase + (size_t)tt * estride);
                __half2 g2 = __float2half2_rn(em * inv);
                __half2 S2 = dot128_h16(r_h[prv], e2h);
                r_h[cur][j] = __low2half(__hmul2(S2, g2));
                __syncthreads();
            }
        }
#pragma unroll 1
        for (; t < fend; ++t) {
            const int cur = t & 1;
            const int prv = cur ^ 1;
            unsigned short ub = __half_as_ushort(r_h[prv][0]);
            int   ke  = (ub >> 10) & 0x1f;
            float inv = __int_as_float((131 - ke) << 23);
            kacc += ke;
            float em = __expf(ering[t & 7]);
            int tt = t + 8; tt = (tt > T_ - 1) ? (T_ - 1) : tt;
            ering[t & 7] = __ldg(ebase + (size_t)tt * estride);
            __half2 g2 = __float2half2_rn(em * inv);
            __half2 S2 = dot128_h16(r_h[prv], e2h);
            r_h[cur][j] = __low2half(__hmul2(S2, g2));
            __syncthreads();
        }
        g_af[bc * N_ + j] = __half2float(r_h[m & 1][j]);
        if (j == 0) g_kf[bc] = kacc;
    } else {
        // ---------------- BACKWARD: nb = len-1-m steps ----------------
        // State pre-multiplied: bt[tau][i] = beta_tau_i * em_tau_i.
        __half2 e2h[64];   // (E[j,2q], E[j,2q+1]) : row j of E (contiguous)
        {
            const float2* tb2 = reinterpret_cast<const float2*>(
                trans + (size_t)c * N_ * N_ + (size_t)j * N_);
#pragma unroll
            for (int q = 0; q < 64; ++q) {
                float2 w = tb2[q];
                e2h[q] = __floats2half2_rn(__expf(w.x), __expf(w.y));
            }
        }
        const int tau0 = len - 1;
        const int nb   = len - 1 - m;
        r_h[0][j] = __float2half_rn(__expf(end_t[c * N_ + j] +
                                           ebase[(size_t)tau0 * estride]));
        __syncthreads();
#pragma unroll
        for (int s0 = 0; s0 < 8; ++s0) {
            int tt = tau0 - 1 - s0; tt = (tt < 0) ? 0 : tt;
            ering[s0] = __ldg(ebase + (size_t)tt * estride);
        }
        int s = 0;
#pragma unroll 1
        for (; s + 7 < nb; s += 8) {
#pragma unroll
            for (int u = 0; u < 8; ++u) {
                const int prv = u & 1;      // s is a multiple of 8
                const int cur = prv ^ 1;
                unsigned short ub = __half_as_ushort(r_h[prv][0]);
                int   ke  = (ub >> 10) & 0x1f;
                float inv = __int_as_float((131 - ke) << 23);
                kacc += ke;
                float em = __expf(ering[(s + u) & 7]);      // emit_{tau0-1-(s+u)}
                int tt = tau0 - 9 - (s + u); tt = (tt < 0) ? 0 : tt;
                ering[(s + u) & 7] = __ldg(ebase + (size_t)tt * estride);
                __half2 g2 = __float2half2_rn(em * inv);
                __half2 S2 = dot128_h16(r_h[prv], e2h);
                r_h[cur][j] = __low2half(__hmul2(S2, g2));
                __syncthreads();
            }
        }
#pragma unroll 1
        for (; s < nb; ++s) {
            const int prv = s & 1;
            const int cur = prv ^ 1;
            unsigned short ub = __half_as_ushort(r_h[prv][0]);
            int   ke  = (ub >> 10) & 0x1f;
            float inv = __int_as_float((131 - ke) << 23);
            kacc += ke;
            float em = __expf(ering[s & 7]);
            int tt = tau0 - 9 - s; tt = (tt < 0) ? 0 : tt;
            ering[s & 7] = __ldg(ebase + (size_t)tt * estride);
            __half2 g2 = __float2half2_rn(em * inv);
            __half2 S2 = dot128_h16(r_h[prv], e2h);
            r_h[cur][j] = __low2half(__hmul2(S2, g2));
            __syncthreads();
        }
        g_bt[bc * N_ + j] = __half2float(r_h[nb & 1][j]);
        if (j == 0) g_kb[bc] = kacc;
    }

    // ---- fused combine (threadFenceReduction pattern): second finisher of
    // each chain reduces and writes out, then resets the flag for replays. ----
    __threadfence();
    __syncthreads();
    if (j == 0) sFlag = atomicAdd(&g_done[bc], 1);
    __syncthreads();
    if (sFlag == 1) {
        float em_m = emissions[(((size_t)b * T_ + m) * C_ + c) * N_ + j];
        float v = g_af[bc * N_ + j] * g_bt[bc * N_ + j] * __expf(-em_m);
#pragma unroll
        for (int o = 16; o > 0; o >>= 1)
            v += __shfl_xor_sync(0xffffffffu, v, o);
        if ((j & 31) == 0) red_sh[j >> 5] = v;
        __syncthreads();
        if (j == 0) {
            float Sf = (red_sh[0] + red_sh[1]) + (red_sh[2] + red_sh[3]);
            float logK = (float)(g_kf[bc] + g_kb[bc] - 4 * (len - 1))
                         * 0.6931471805599453f;
            out[bc] = logK + logf(Sf);
            __threadfence();
            g_done[bc] = 0;               // clean state for next graph replay
        }
    }
}

extern "C" void kernel_launch(void* const* d_in, const int* in_sizes, int n_in,
                              void* d_out, int out_size) {
    const float* emissions = nullptr;
    const int*   lengths   = nullptr;
    const float* trans     = nullptr;
    const float* start_t   = nullptr;
    const float* end_t     = nullptr;

    for (int i = 0; i < n_in; ++i) {
        int sz = in_sizes[i];
        if (sz == B_ * T_ * C_ * N_)      emissions = (const float*)d_in[i];
        else if (sz == B_)                lengths   = (const int*)d_in[i];
        else if (sz == C_ * N_ * N_)      trans     = (const float*)d_in[i];
    }
    if (n_in > 3 && in_sizes[3] == C_ * N_) start_t = (const float*)d_in[3];
    for (int i = 0; i < n_in; ++i) {
        if (in_sizes[i] == C_ * N_ && (const float*)d_in[i] != start_t)
            end_t = (const float*)d_in[i];
    }
    if (!start_t) {
        for (int i = 0; i < n_in; ++i)
            if (in_sizes[i] == C_ * N_) { start_t = (const float*)d_in[i]; break; }
        for (int i = 0; i < n_in; ++i)
            if (in_sizes[i] == C_ * N_ && (const float*)d_in[i] != start_t)
                end_t = (const float*)d_in[i];
    }

    float* out = (float*)d_out;
    crf_bidir_kernel<<<2 * B_ * C_, N_>>>(emissions, lengths, trans,
                                          start_t, end_t, out);
}

// round 17
// speedup vs baseline: 1.1725x; 1.1725x over previous
#include <cuda_runtime.h>
#include <cuda_fp16.h>

#define B_ 64
#define T_ 1024
#define C_ 2
#define N_ 128

// Scratch (static __device__: allowed; no dynamic allocation).
__device__ float g_af[B_ * C_ * N_];   // alpha_hat_m  (forward, normalized)
__device__ float g_bt[B_ * C_ * N_];   // beta_tilde_m (backward, normalized, * em)
__device__ int   g_kf[B_ * C_];
__device__ int   g_kb[B_ * C_];
__device__ int   g_assign[2 * B_ * C_]; // bid -> work item (role*128 + bc)
__device__ int   g_done[B_ * C_];       // zero-init; combiner resets after use

// ---- scheduler (R14, symmetric): rank 256 half-chain items by step count,
// longest 40 -> solo SMs (bids 108..147), rest pair longest-with-shortest
// (bid k and bid k+148 share an SM: LUT_classic[bid % 148]).
__global__ void __launch_bounds__(256, 1)
crf_sched_kernel(const int* __restrict__ lengths) {
    __shared__ int sl[B_];
    int i = threadIdx.x;                 // work item 0..255
    if (i < B_) sl[i] = lengths[i];
    __syncthreads();

    int bc   = i & 127;
    int role = i >> 7;
    int len  = sl[bc >> 1];
    int m    = (len - 1) >> 1;
    int steps = role ? (len - 1 - m) : m;

    int rank = 0;
    for (int k = 0; k < 256; ++k) {
        int lk = sl[(k & 127) >> 1];
        int mk = (lk - 1) >> 1;
        int sk = (k >> 7) ? (lk - 1 - mk) : mk;
        rank += (sk > steps) || (sk == steps && k < i);
    }
    int bid;
    if (rank < 40)        bid = 108 + rank;        // longest 40: solo SMs
    else if (rank < 148)  bid = rank - 40;         // first slot of doubled SMs
    else                  bid = 148 + (255 - rank);// second slot, reversed pairing
    g_assign[bid] = i;
}

// fp16 dot over 128 elements, fp16 epilogue: total in BOTH halves of result.
__device__ __forceinline__ __half2 dot128_h16(const __half* rbuf, const __half2* e2h) {
    const uint4* pv = reinterpret_cast<const uint4*>(rbuf);
    __half2 a0 = __float2half2_rn(0.f), a1 = a0, a2 = a0, a3 = a0;
#pragma unroll
    for (int k = 0; k < 16; ++k) {
        uint4 v = pv[k];
        a0 = __hfma2(e2h[4 * k + 0], *reinterpret_cast<const __half2*>(&v.x), a0);
        a1 = __hfma2(e2h[4 * k + 1], *reinterpret_cast<const __half2*>(&v.y), a1);
        a2 = __hfma2(e2h[4 * k + 2], *reinterpret_cast<const __half2*>(&v.z), a2);
        a3 = __hfma2(e2h[4 * k + 3], *reinterpret_cast<const __half2*>(&v.w), a3);
    }
    __half2 A  = __hadd2(a0, a1);
    __half2 Bb = __hadd2(a2, a3);
    __half2 Cc = __hadd2(A, Bb);
    return __hadd2(Cc, __lowhigh2highlow(Cc));
}

// Half-chain scan + fused combine (threadFenceReduction pattern): the second
// finisher of each chain reduces that chain and writes out[bc].
__global__ void __launch_bounds__(128, 2)
crf_bidir_kernel(const float* __restrict__ emissions,   // [B,T,C,N]
                 const int*   __restrict__ lengths,     // [B]
                 const float* __restrict__ trans,       // [1,C,N,N]
                 const float* __restrict__ start_t,     // [1,C,N]
                 const float* __restrict__ end_t,       // [1,C,N]
                 float*       __restrict__ out)         // [B,C]
{
    const int j    = threadIdx.x;
    const int item = g_assign[blockIdx.x];
    const int role = item >> 7;           // 0 = forward, 1 = backward
    const int bc   = item & 127;
    const int b    = bc >> 1;
    const int c    = bc & 1;
    const int len  = lengths[b];          // in [T/2, T]
    const int m    = (len - 1) >> 1;      // symmetric meeting point

    __shared__ __align__(16) __half r_h[2][N_];
    __shared__ float red_sh[4];
    __shared__ int sFlag;

    const float* ebase = emissions + ((size_t)b * T_ * C_ + c) * N_ + j;
    const int estride = C_ * N_;
    int kacc = 0;
    float ering[8];

    if (role == 0) {
        // ---------------- FORWARD: steps t = 1..m ----------------
        __half2 e2h[64];   // (E[2q,j], E[2q+1,j]) : column j of E
        {
            const float* tb = trans + (size_t)c * N_ * N_ + j;
#pragma unroll
            for (int q = 0; q < 64; ++q) {
                float lo = __expf(tb[(size_t)(2 * q) * N_]);
                float hi = __expf(tb[(size_t)(2 * q + 1) * N_]);
                e2h[q] = __floats2half2_rn(lo, hi);
            }
        }
        r_h[0][j] = __float2half_rn(__expf(start_t[c * N_ + j] + ebase[0]));
        __syncthreads();
#pragma unroll
        for (int d = 1; d <= 8; ++d)
            ering[d & 7] = __ldg(ebase + (size_t)d * estride);

        const int fend = m + 1;
        int t = 1;
#pragma unroll 1
        for (; t + 7 < fend; t += 8) {
#pragma unroll
            for (int u = 0; u < 8; ++u) {
                const int cur  = (1 + u) & 1;
                const int prv  = cur ^ 1;
                const int slot = (1 + u) & 7;
                unsigned short ub = __half_as_ushort(r_h[prv][0]);
                int   ke  = (ub >> 10) & 0x1f;
                float inv = __int_as_float((131 - ke) << 23);   // 2^(4-ke)
                kacc += ke;
                float em = __expf(ering[slot]);
                int tt = t + u + 8; tt = (tt > T_ - 1) ? (T_ - 1) : tt;
                ering[slot] = __ldg(ebase + (size_t)tt * estride);
                __half2 g2 = __float2half2_rn(em * inv);
                __half2 S2 = dot128_h16(r_h[prv], e2h);
                r_h[cur][j] = __low2half(__hmul2(S2, g2));
                __syncthreads();
            }
        }
#pragma unroll 1
        for (; t < fend; ++t) {
            const int cur = t & 1;
            const int prv = cur ^ 1;
            unsigned short ub = __half_as_ushort(r_h[prv][0]);
            int   ke  = (ub >> 10) & 0x1f;
            float inv = __int_as_float((131 - ke) << 23);
            kacc += ke;
            float em = __expf(ering[t & 7]);
            int tt = t + 8; tt = (tt > T_ - 1) ? (T_ - 1) : tt;
            ering[t & 7] = __ldg(ebase + (size_t)tt * estride);
            __half2 g2 = __float2half2_rn(em * inv);
            __half2 S2 = dot128_h16(r_h[prv], e2h);
            r_h[cur][j] = __low2half(__hmul2(S2, g2));
            __syncthreads();
        }
        g_af[bc * N_ + j] = __half2float(r_h[m & 1][j]);
        if (j == 0) g_kf[bc] = kacc;
    } else {
        // ---------------- BACKWARD: nb = len-1-m steps ----------------
        // State pre-multiplied: bt[tau][i] = beta_tau_i * em_tau_i.
        __half2 e2h[64];   // (E[j,2q], E[j,2q+1]) : row j of E (contiguous)
        {
            const float2* tb2 = reinterpret_cast<const float2*>(
                trans + (size_t)c * N_ * N_ + (size_t)j * N_);
#pragma unroll
            for (int q = 0; q < 64; ++q) {
                float2 w = tb2[q];
                e2h[q] = __floats2half2_rn(__expf(w.x), __expf(w.y));
            }
        }
        const int tau0 = len - 1;
        const int nb   = len - 1 - m;
        r_h[0][j] = __float2half_rn(__expf(end_t[c * N_ + j] +
                                           ebase[(size_t)tau0 * estride]));
        __syncthreads();
#pragma unroll
        for (int s0 = 0; s0 < 8; ++s0) {
            int tt = tau0 - 1 - s0; tt = (tt < 0) ? 0 : tt;
            ering[s0] = __ldg(ebase + (size_t)tt * estride);
        }
        int s = 0;
#pragma unroll 1
        for (; s + 7 < nb; s += 8) {
#pragma unroll
            for (int u = 0; u < 8; ++u) {
                const int prv = u & 1;      // s is a multiple of 8
                const int cur = prv ^ 1;
                unsigned short ub = __half_as_ushort(r_h[prv][0]);
                int   ke  = (ub >> 10) & 0x1f;
                float inv = __int_as_float((131 - ke) << 23);
                kacc += ke;
                float em = __expf(ering[(s + u) & 7]);      // emit_{tau0-1-(s+u)}
                int tt = tau0 - 9 - (s + u); tt = (tt < 0) ? 0 : tt;
                ering[(s + u) & 7] = __ldg(ebase + (size_t)tt * estride);
                __half2 g2 = __float2half2_rn(em * inv);
                __half2 S2 = dot128_h16(r_h[prv], e2h);
                r_h[cur][j] = __low2half(__hmul2(S2, g2));
                __syncthreads();
            }
        }
#pragma unroll 1
        for (; s < nb; ++s) {
            const int prv = s & 1;
            const int cur = prv ^ 1;
            unsigned short ub = __half_as_ushort(r_h[prv][0]);
            int   ke  = (ub >> 10) & 0x1f;
            float inv = __int_as_float((131 - ke) << 23);
            kacc += ke;
            float em = __expf(ering[s & 7]);
            int tt = tau0 - 9 - s; tt = (tt < 0) ? 0 : tt;
            ering[s & 7] = __ldg(ebase + (size_t)tt * estride);
            __half2 g2 = __float2half2_rn(em * inv);
            __half2 S2 = dot128_h16(r_h[prv], e2h);
            r_h[cur][j] = __low2half(__hmul2(S2, g2));
            __syncthreads();
        }
        g_bt[bc * N_ + j] = __half2float(r_h[nb & 1][j]);
        if (j == 0) g_kb[bc] = kacc;
    }

    // ---- fused combine: second finisher of chain bc reduces + writes out ----
    __threadfence();
    __syncthreads();
    if (j == 0) sFlag = atomicAdd(&g_done[bc], 1);
    __syncthreads();
    if (sFlag == 1) {
        float em_m = emissions[(((size_t)b * T_ + m) * C_ + c) * N_ + j];
        float v = g_af[bc * N_ + j] * g_bt[bc * N_ + j] * __expf(-em_m);
#pragma unroll
        for (int o = 16; o > 0; o >>= 1)
            v += __shfl_xor_sync(0xffffffffu, v, o);
        if ((j & 31) == 0) red_sh[j >> 5] = v;
        __syncthreads();
        if (j == 0) {
            float Sf = (red_sh[0] + red_sh[1]) + (red_sh[2] + red_sh[3]);
            float logK = (float)(g_kf[bc] + g_kb[bc] - 4 * (len - 1))
                         * 0.6931471805599453f;
            out[bc] = logK + logf(Sf);
            __threadfence();
            g_done[bc] = 0;               // clean state for next graph replay
        }
    }
}

extern "C" void kernel_launch(void* const* d_in, const int* in_sizes, int n_in,
                              void* d_out, int out_size) {
    const float* emissions = nullptr;
    const int*   lengths   = nullptr;
    const float* trans     = nullptr;
    const float* start_t   = nullptr;
    const float* end_t     = nullptr;

    for (int i = 0; i < n_in; ++i) {
        int sz = in_sizes[i];
        if (sz == B_ * T_ * C_ * N_)      emissions = (const float*)d_in[i];
        else if (sz == B_)                lengths   = (const int*)d_in[i];
        else if (sz == C_ * N_ * N_)      trans     = (const float*)d_in[i];
    }
    if (n_in > 3 && in_sizes[3] == C_ * N_) start_t = (const float*)d_in[3];
    for (int i = 0; i < n_in; ++i) {
        if (in_sizes[i] == C_ * N_ && (const float*)d_in[i] != start_t)
            end_t = (const float*)d_in[i];
    }
    if (!start_t) {
        for (int i = 0; i < n_in; ++i)
            if (in_sizes[i] == C_ * N_) { start_t = (const float*)d_in[i]; break; }
        for (int i = 0; i < n_in; ++i)
            if (in_sizes[i] == C_ * N_ && (const float*)d_in[i] != start_t)
                end_t = (const float*)d_in[i];
    }

    float* out = (float*)d_out;
    crf_sched_kernel<<<1, 256>>>(lengths);
    crf_bidir_kernel<<<2 * B_ * C_, N_>>>(emissions, lengths, trans,
                                          start_t, end_t, out);
}